// round 15
// baseline (speedup 1.0000x reference)
#include <cuda_runtime.h>
#include <math.h>

#define Bq 4
#define IMG 128
#define HW (IMG*IMG)          // 16384
#define NF 64
#define CUBE 26
#define VOX (CUBE*CUBE*CUBE)  // 17576
#define FIN 448
#define FH 64
#define FOUT 128
#define PROWS 512
#define OUTC 193
#define LATD 512
#define STATE 32832
#define PTOT 98688
#define N_CALLS 4

#define OFF_W1 0
#define OFF_B1 28672
#define OFF_W2 28736
#define OFF_B2 32832
#define OFF_W3 32896
#define OFF_B3 41088
#define OFF_WSH 41216
#define OFF_BSH 98560

// ---------------- scratch ------------------------------------------------------
__device__ float g_h0[Bq*NF*HW];
__device__ float g_t1[Bq*NF*HW];
__device__ float g_hrb[Bq*NF*HW];
__device__ float g_carry[Bq*NF*VOX];
__device__ float g_p[(long)Bq*PROWS*VOX];
__device__ float g_hh[Bq*NF*VOX];
__device__ float g_mean[Bq*FIN];
__device__ float g_inv[Bq*FIN];
__device__ float g_dp[Bq*PTOT];
__device__ float g_w1f[Bq*FH*FIN];
__device__ float g_b1f[Bq*FH];
__device__ float g_wcat[Bq*FOUT*PROWS];
__device__ float g_bcat[Bq*FOUT];
__device__ float g_f[Bq*OUTC*HW];
__device__ float g_state[Bq*STATE];
__device__ float g_part[1<<20];
__device__ float g_s1[Bq*2*LATD];
__device__ float g_s2[Bq*LATD];
__device__ float g_s3[Bq*LATD];

// ---------------- f32x2 helpers ----------------------------------------------
__device__ __forceinline__ unsigned long long pk2(float lo, float hi){
    unsigned long long r;
    asm("mov.b64 %0, {%1,%2};" : "=l"(r) : "f"(lo), "f"(hi));
    return r;
}
__device__ __forceinline__ void upk2(unsigned long long v, float& lo, float& hi){
    asm("mov.b64 {%0,%1}, %2;" : "=f"(lo), "=f"(hi) : "l"(v));
}
__device__ __forceinline__ void fma2(unsigned long long& d, unsigned long long a,
                                     unsigned long long b){
    asm("fma.rn.f32x2 %0, %1, %2, %0;" : "+l"(d) : "l"(a), "l"(b));
}
__device__ __forceinline__ float fast_sigmoid(float g){
    return __fdividef(1.f, 1.f + __expf(-g));
}

// ---------------- FFMA2 SGEMM (R10 config), deferred A-store --------------------
// mode 0: store (+D);  mode 1: lrelu store;  mode 2: gated carry accumulate.
template<int BM, int TM, int MB>
__global__ void __launch_bounds__(256, MB) gemm_k(
    const float* __restrict__ A, long sA,
    const float* __restrict__ Bm, long sB, int ldB,
    float* __restrict__ C, long sC, int ldC,
    const float* __restrict__ bias, long sBias,
    const float* __restrict__ D, long sD, int ldD,
    int M, int N, int K, int mode,
    const float* __restrict__ leakp)
{
    constexpr int BK = 16;
    constexpr int APAD = BM + 4;
    constexpr int APT = BM/64;
    __shared__ __align__(16) float As[2][BK][APAD];
    __shared__ __align__(16) float Bs[2][BK][128];

    int b = blockIdx.z;
    A  += (long)b*sA;
    Bm += (long)b*sB;
    C  += (long)b*sC;
    const float* biasb = bias ? bias + (long)b*sBias : nullptr;
    const float* Db    = D    ? D    + (long)b*sD    : nullptr;

    int n0 = blockIdx.x*128;
    int m0 = blockIdx.y*BM;
    int tid = threadIdx.x;
    int tx = tid & 15, ty = tid >> 4;

    unsigned long long acc[TM][4];
#pragma unroll
    for (int i=0;i<TM;i++)
#pragma unroll
        for (int j=0;j<4;j++) acc[i][j] = 0ULL;

    int nk = K / BK;
    float4 ra[APT];

    auto ldAr = [&](int kt){
#pragma unroll
        for (int c=0;c<APT;c++){
            int q = tid + c*256;
            int row = q >> 2, ks = (q & 3)*4;
            int m = m0 + row;
            ra[c] = (m < M) ? *(const float4*)(A + (long)m*K + kt*BK + ks)
                            : make_float4(0.f,0.f,0.f,0.f);
        }
    };
    auto stAr = [&](int bw){
#pragma unroll
        for (int c=0;c<APT;c++){
            int q = tid + c*256;
            int row = q >> 2, ks = (q & 3)*4;
            As[bw][ks+0][row] = ra[c].x;
            As[bw][ks+1][row] = ra[c].y;
            As[bw][ks+2][row] = ra[c].z;
            As[bw][ks+3][row] = ra[c].w;
        }
    };
    auto ldBa = [&](int bw, int kt){
#pragma unroll
        for (int c=0;c<2;c++){
            int q = tid + c*256;
            int k = q >> 5, seg = q & 31;
            int n = n0 + seg*4;
            const float* src = Bm + (long)(kt*BK+k)*ldB + n;
            int sz = 16;
            if (n >= N){ sz = 0; src = Bm; }
            unsigned dst = (unsigned)__cvta_generic_to_shared(&Bs[bw][k][seg*4]);
            asm volatile("cp.async.cg.shared.global [%0], [%1], 16, %2;"
                         :: "r"(dst), "l"(src), "r"(sz));
        }
    };

    ldAr(0);
    ldBa(0, 0);
    asm volatile("cp.async.commit_group;");
    stAr(0);

    int buf = 0;
    for (int kt=0; kt<nk; kt++){
        asm volatile("cp.async.wait_group 0;");
        __syncthreads();
        bool more = (kt+1 < nk);
        if (more){
            ldAr(kt+1);
            ldBa(buf^1, kt+1);
            asm volatile("cp.async.commit_group;");
        }
#pragma unroll
        for (int kk=0; kk<BK; kk++){
            float a[TM];
            *(float4*)&a[0] = *(const float4*)&As[buf][kk][ty*TM];
            if (TM == 8)
                *(float4*)&a[4] = *(const float4*)&As[buf][kk][ty*TM+4];
            ulonglong2 bp01 = *(const ulonglong2*)&Bs[buf][kk][tx*4];
            ulonglong2 bp23 = *(const ulonglong2*)&Bs[buf][kk][64 + tx*4];
#pragma unroll
            for (int i=0;i<TM;i++){
                unsigned long long ap = pk2(a[i], a[i]);
                fma2(acc[i][0], ap, bp01.x);
                fma2(acc[i][1], ap, bp01.y);
                fma2(acc[i][2], ap, bp23.x);
                fma2(acc[i][3], ap, bp23.y);
            }
        }
        if (more) stAr(buf^1);
        buf ^= 1;
    }

    float cv[TM][8];
#pragma unroll
    for (int i=0;i<TM;i++)
#pragma unroll
        for (int j=0;j<4;j++) upk2(acc[i][j], cv[i][2*j], cv[i][2*j+1]);

    if (mode == 2){
        float lk = fminf(fmaxf(leakp[0], 0.001f), 1000.f);
#pragma unroll
        for (int i=0;i<TM;i+=2){
            int m = m0 + ty*TM + i;
            int gg = m >> 1;
            float bv = biasb[m], bgt = biasb[m+1];
#pragma unroll
            for (int h=0;h<2;h++){
                int n = n0 + h*64 + tx*4;
                if (n < N){
                    float* cp = C + (long)gg*ldC + n;
                    float4 c = *(float4*)cp;
                    float vv[4], gv[4];
#pragma unroll
                    for (int e=0;e<4;e++){
                        vv[e] = cv[i][h*4+e]   + bv;
                        gv[e] = cv[i+1][h*4+e] + bgt;
                    }
                    c.x += lk*vv[0]*fast_sigmoid(gv[0]);
                    c.y += lk*vv[1]*fast_sigmoid(gv[1]);
                    c.z += lk*vv[2]*fast_sigmoid(gv[2]);
                    c.w += lk*vv[3]*fast_sigmoid(gv[3]);
                    *(float4*)cp = c;
                }
            }
        }
    } else {
#pragma unroll
        for (int i=0;i<TM;i++){
            int m = m0 + ty*TM + i;
            if (m >= M) continue;
            float bvv = biasb ? biasb[m] : 0.f;
#pragma unroll
            for (int h=0;h<2;h++){
                int n = n0 + h*64 + tx*4;
                if (n < N){
                    float4 v = make_float4(cv[i][h*4+0]+bvv, cv[i][h*4+1]+bvv,
                                           cv[i][h*4+2]+bvv, cv[i][h*4+3]+bvv);
                    if (Db){
                        float4 d = *(const float4*)(Db + (long)m*ldD + n);
                        v.x += d.x; v.y += d.y; v.z += d.z; v.w += d.w;
                    }
                    if (mode == 1){
                        v.x = v.x>0.f ? v.x : 0.2f*v.x;
                        v.y = v.y>0.f ? v.y : 0.2f*v.y;
                        v.z = v.z>0.f ? v.z : 0.2f*v.z;
                        v.w = v.w>0.f ? v.w : 0.2f*v.w;
                    }
                    *(float4*)(C + (long)m*ldC + n) = v;
                }
            }
        }
    }
}

// ---------------- elementwise ----------------------------------------------------
__global__ void conv1_k(const float* __restrict__ x, const float* __restrict__ w,
                        const float* __restrict__ bias){
    int idx = blockIdx.x*blockDim.x+threadIdx.x;
    if (idx >= Bq*NF*HW) return;
    int pix = idx % HW;
    int o = (idx/HW)%NF;
    int b = idx/(NF*HW);
    const float* xb = x + (long)b*3*HW + pix;
    g_h0[idx] = xb[0]*w[o*3] + xb[HW]*w[o*3+1] + xb[2*HW]*w[o*3+2] + bias[o];
}

__global__ void pad_k(){
    int idx = blockIdx.x*blockDim.x+threadIdx.x;
    if (idx >= Bq*NF*VOX) return;
    int v = idx % VOX;
    int bc = idx / VOX;
    g_carry[idx] = (v < HW) ? g_hrb[(long)bc*HW + v] : 0.f;
}

// ---------------- sobel + stats: interior fast path / boundary slow path ---------
#define CC2 (CUBE*CUBE)
__global__ void sobel_k(){
    extern __shared__ float sc[];
    __shared__ float wsum[16][7], wsq[16][7];
    int bg = blockIdx.x;
    int gch = bg & 63, b = bg >> 6;
    int tid = threadIdx.x;
    int warp = tid >> 5, lane = tid & 31;
    const float* in = g_carry + (long)bg*VOX;
    for (int i=tid;i<VOX;i+=512) sc[i] = in[i];
    __syncthreads();

    float sum[7], sq[7];
#pragma unroll
    for (int t=0;t<7;t++){ sum[t]=0.f; sq[t]=0.f; }

    int ch[7] = {gch, 64+3*gch, 64+3*gch+1, 64+3*gch+2, 256+3*gch, 256+3*gch+1, 256+3*gch+2};
    float* pb = g_p + (long)b*PROWS*VOX;

    const float g5[5] = {-1.f, -0.70710678f, 0.f, 0.70710678f, 1.f};
    const float s5[3] = {0.70710678f, 1.f, 0.70710678f};

    // ---- interior: 22^3 voxels, compile-time tap offsets, no bound checks ----
    const int IN1 = 22, IN2 = 22*22, IN3 = 22*22*22;
    for (int t=tid; t<IN3; t+=512){
        int d = t/IN2;
        int r = t - d*IN2;
        int h = r/IN1;
        int w = r - h*IN1;
        int v = (d+2)*CC2 + (h+2)*CUBE + (w+2);
        const float* cp = sc + v;

        float c = cp[0];
        float gx3 = cp[CC2]-cp[-CC2];
        float gy3 = cp[CUBE]-cp[-CUBE];
        float gz3 = cp[1]-cp[-1];

        float gx5=0.f, gy5=0.f, gz5=0.f;
#pragma unroll
        for (int a=0;a<5;a++){
            if (a==2) continue;
            float ga = g5[a];
#pragma unroll
            for (int i=-1;i<=1;i++){
#pragma unroll
                for (int j=-1;j<=1;j++){
                    float sij = ga * s5[i+1]*s5[j+1];
                    gx5 += sij * cp[(a-2)*CC2 + i*CUBE + j];
                    gy5 += sij * cp[i*CC2 + (a-2)*CUBE + j];
                    gz5 += sij * cp[i*CC2 + j*CUBE + (a-2)];
                }
            }
        }
        float o[7] = {c, gx3, gy3, gz3, gx5, gy5, gz5};
#pragma unroll
        for (int t2=0;t2<7;t2++){
            pb[(long)ch[t2]*VOX + v] = o[t2];
            sum[t2] += o[t2];
            sq[t2]  += o[t2]*o[t2];
        }
    }

    // ---- boundary: remaining voxels with bound-checked taps ----
    auto at = [&](int d,int h,int w)->float{
        if ((unsigned)d>=CUBE || (unsigned)h>=CUBE || (unsigned)w>=CUBE) return 0.f;
        return sc[(d*CUBE+h)*CUBE+w];
    };
    for (int v=tid; v<VOX; v+=512){
        int d = v/CC2;
        int r = v%CC2;
        int h = r/CUBE, w = r%CUBE;
        if (d>=2 && d<CUBE-2 && h>=2 && h<CUBE-2 && w>=2 && w<CUBE-2) continue;

        float c = sc[v];
        float gx3 = at(d+1,h,w) - at(d-1,h,w);
        float gy3 = at(d,h+1,w) - at(d,h-1,w);
        float gz3 = at(d,h,w+1) - at(d,h,w-1);

        float gx5=0.f, gy5=0.f, gz5=0.f;
#pragma unroll
        for (int a=0;a<5;a++){
            if (a==2) continue;
            float ga = g5[a];
#pragma unroll
            for (int i=-1;i<=1;i++){
#pragma unroll
                for (int j=-1;j<=1;j++){
                    float sij = ga * s5[i+1]*s5[j+1];
                    gx5 += sij * at(d+a-2, h+i,   w+j);
                    gy5 += sij * at(d+i,   h+a-2, w+j);
                    gz5 += sij * at(d+i,   h+j,   w+a-2);
                }
            }
        }
        float o[7] = {c, gx3, gy3, gz3, gx5, gy5, gz5};
#pragma unroll
        for (int t2=0;t2<7;t2++){
            pb[(long)ch[t2]*VOX + v] = o[t2];
            sum[t2] += o[t2];
            sq[t2]  += o[t2]*o[t2];
        }
    }

#pragma unroll
    for (int t=0;t<7;t++){
#pragma unroll
        for (int off=16; off>0; off>>=1){
            sum[t] += __shfl_down_sync(0xffffffffu, sum[t], off);
            sq[t]  += __shfl_down_sync(0xffffffffu, sq[t],  off);
        }
        if (lane==0){ wsum[warp][t]=sum[t]; wsq[warp][t]=sq[t]; }
    }
    __syncthreads();
    if (tid < 7){
        double s=0.0, q=0.0;
        for (int w=0; w<16; w++){ s += (double)wsum[w][tid]; q += (double)wsq[w][tid]; }
        double m = s*(1.0/VOX);
        double var = q*(1.0/VOX) - m*m;
        g_mean[b*FIN + ch[tid]] = (float)m;
        g_inv [b*FIN + ch[tid]] = rsqrtf((float)var + 1e-5f);
    }
}

// ---------------- fold inorm into hypernet weights (interleaved wcat) -------------
__global__ void fold_k(){
    int r = blockIdx.x, b = blockIdx.y;
    int tid = threadIdx.x;
    __shared__ float red[128];
    const float* dpb = g_dp + (long)b*PTOT;
    const float* mv = g_mean + b*FIN;
    const float* iv = g_inv  + b*FIN;

    if (r < 64){
        int o = r;
        const float* wsrc = dpb + OFF_W1 + o*FIN;
        float* wd = g_w1f + ((long)b*FH + o)*FIN;
        float dot = 0.f;
        for (int i=tid;i<FIN;i+=128){
            float wi = wsrc[i]*iv[i];
            wd[i] = wi;
            dot += wi*mv[i];
        }
        red[tid]=dot; __syncthreads();
        for (int s=64;s>0;s>>=1){ if (tid<s) red[tid]+=red[tid+s]; __syncthreads(); }
        if (tid==0) g_b1f[b*FH+o] = dpb[OFF_B1+o] - red[0];
    } else {
        int rr = r - 64;                 // interleaved: row 2g=val g, 2g+1=gate g
        int gg = rr >> 1, e = rr & 1;
        int o = e*64 + gg;
        const float* wsh = dpb + OFF_WSH + o*FIN;
        const float* w3  = dpb + OFF_W3  + o*FH;
        float* wd = g_wcat + ((long)b*FOUT + rr)*PROWS;
        float dot = 0.f;
        for (int i=tid;i<FIN;i+=128){
            float wi = wsh[i]*iv[i];
            wd[i] = wi;
            dot += wi*mv[i];
        }
        if (tid < 64) wd[FIN + tid] = w3[tid];
        red[tid]=dot; __syncthreads();
        for (int s=64;s>0;s>>=1){ if (tid<s) red[tid]+=red[tid+s]; __syncthreads(); }
        if (tid==0) g_bcat[b*FOUT+rr] = dpb[OFF_B3+o] + dpb[OFF_BSH+o] - red[0];
    }
}

// ---------------- state assembly ---------------------------------------------------
__global__ void cf_k(){
    int bc = blockIdx.x;
    int b = bc/NF, c = bc%NF;
    const float* x = g_f + ((long)b*OUTC + c)*HW;
    __shared__ float red[256];
    int tid = threadIdx.x;
    float s=0.f;
    for (int i=tid;i<HW;i+=256) s += x[i];
    red[tid]=s; __syncthreads();
    for (int st=128;st>0;st>>=1){ if (tid<st) red[tid]+=red[tid+st]; __syncthreads(); }
    if (tid==0) g_state[(long)b*STATE + c] = red[0]*(1.f/HW);
}
__global__ void cfh_k(){
    int bc = blockIdx.x; int b = bc/NF, c = bc%NF;
    int h = threadIdx.x;
    const float* x = g_f + ((long)b*OUTC + 64 + c)*HW + h*IMG;
    float s=0.f;
    for (int w=0;w<IMG;w++) s += x[w];
    g_state[(long)b*STATE + 64 + c*IMG + h] = s*(1.f/IMG);
}
__global__ void cfw_k(){
    int bc = blockIdx.x; int b = bc/NF, c = bc%NF;
    int w = threadIdx.x;
    const float* x = g_f + ((long)b*OUTC + 128 + c)*HW + w;
    float s=0.f;
    for (int h=0;h<IMG;h++) s += x[h*IMG];
    g_state[(long)b*STATE + 8256 + c*IMG + w] = s*(1.f/IMG);
}
__global__ void chw_k(){
    int idx = blockIdx.x*blockDim.x+threadIdx.x;
    if (idx >= Bq*HW) return;
    int b = idx/HW, i = idx%HW;
    g_state[(long)b*STATE + 16448 + i] = g_f[((long)b*OUTC + 192)*HW + i];
}

// ---------------- skinny (M=4) GEMM: deterministic split-K ------------------------
__global__ void skinny_k(const float* __restrict__ X, const float* __restrict__ W,
                         int K, int O, int nCh){
    int o = blockIdx.x*256 + threadIdx.x;
    int ch = blockIdx.y;
    if (o >= O) return;
    long k0 = ((long)K*ch)/nCh, k1 = ((long)K*(ch+1))/nCh;
    float a0=0.f,a1=0.f,a2=0.f,a3=0.f;
    for (long k=k0;k<k1;k++){
        float wv = W[k*O + o];
        a0 += __ldg(&X[k])      *wv;
        a1 += __ldg(&X[K+k])    *wv;
        a2 += __ldg(&X[2L*K+k]) *wv;
        a3 += __ldg(&X[3L*K+k]) *wv;
    }
    long base = (long)ch*4*O + o;
    g_part[base]        = a0;
    g_part[base+O]      = a1;
    g_part[base+2L*O]   = a2;
    g_part[base+3L*O]   = a3;
}

__global__ void skinny_epi_k(int nCh, int O, const float* __restrict__ bias,
                             const float* __restrict__ add, float* __restrict__ out,
                             int act){
    int idx = blockIdx.x*256+threadIdx.x;
    if (idx >= 4*O) return;
    int b = idx/O, o = idx%O;
    float s=0.f;
    for (int ch=0;ch<nCh;ch++) s += g_part[(long)ch*4*O + (long)b*O + o];
    if (bias) s += bias[o];
    if (add)  s += add[idx];
    if (act)  s = s>0.f ? s : 0.2f*s;
    out[idx]=s;
}

// ---------------- launch orchestration ---------------------------------------------
extern "C" void kernel_launch(void* const* d_in, const int* in_sizes, int n_in,
                              void* d_out, int out_size)
{
    const float* x        = (const float*)d_in[0];
    const float* inj_lat  = (const float*)d_in[1];
    const float* in_w     = (const float*)d_in[2];
    const float* in_b     = (const float*)d_in[3];
    const float* rbin_w1  = (const float*)d_in[4];
    const float* rbin_b1  = (const float*)d_in[5];
    const float* rbin_w2  = (const float*)d_in[6];
    const float* rbin_b2  = (const float*)d_in[7];
    const float* leak     = (const float*)d_in[8];
    const float* hyper_w  = (const float*)d_in[9];
    const float* hyper_b  = (const float*)d_in[10];
    const float* rbout_w1 = (const float*)d_in[11];
    const float* rbout_b1 = (const float*)d_in[12];
    const float* rbout_w2 = (const float*)d_in[13];
    const float* rbout_b2 = (const float*)d_in[14];
    const float* outc_w   = (const float*)d_in[15];
    const float* outc_b   = (const float*)d_in[16];
    const float* l1a_w    = (const float*)d_in[17];
    const float* l1a_b    = (const float*)d_in[18];
    const float* l1b_w    = (const float*)d_in[19];
    const float* l1b_b    = (const float*)d_in[20];
    const float* l1s_w    = (const float*)d_in[21];
    const float* l2a_w    = (const float*)d_in[22];
    const float* l2a_b    = (const float*)d_in[23];
    const float* l2b_w    = (const float*)d_in[24];
    const float* l2b_b    = (const float*)d_in[25];
    const float* lat_w    = (const float*)d_in[26];
    const float* lat_b    = (const float*)d_in[27];
    float* out = (float*)d_out;

    float *h0, *t1, *hrb, *carry, *p, *hh, *dp, *f, *state, *s1, *s2, *s3;
    float *w1f, *b1f, *wcat, *bcat;
    cudaGetSymbolAddress((void**)&h0,    g_h0);
    cudaGetSymbolAddress((void**)&t1,    g_t1);
    cudaGetSymbolAddress((void**)&hrb,   g_hrb);
    cudaGetSymbolAddress((void**)&carry, g_carry);
    cudaGetSymbolAddress((void**)&p,     g_p);
    cudaGetSymbolAddress((void**)&hh,    g_hh);
    cudaGetSymbolAddress((void**)&dp,    g_dp);
    cudaGetSymbolAddress((void**)&f,     g_f);
    cudaGetSymbolAddress((void**)&state, g_state);
    cudaGetSymbolAddress((void**)&s1,    g_s1);
    cudaGetSymbolAddress((void**)&s2,    g_s2);
    cudaGetSymbolAddress((void**)&s3,    g_s3);
    cudaGetSymbolAddress((void**)&w1f,   g_w1f);
    cudaGetSymbolAddress((void**)&b1f,   g_b1f);
    cudaGetSymbolAddress((void**)&wcat,  g_wcat);
    cudaGetSymbolAddress((void**)&bcat,  g_bcat);

    cudaFuncSetAttribute(sobel_k, cudaFuncAttributeMaxDynamicSharedMemorySize,
                         VOX*(int)sizeof(float));

    const int gHW  = HW/128;            // 128
    const int gVOX = (VOX+127)/128;     // 138

    // ---- hypernetwork
    skinny_k<<<dim3((PTOT+255)/256, 2), 256>>>(inj_lat, hyper_w, LATD, PTOT, 2);
    skinny_epi_k<<<(4*PTOT+255)/256, 256>>>(2, PTOT, hyper_b, nullptr, dp, 0);

    // ---- input conv1x1 + rb2d_in
    conv1_k<<<(Bq*NF*HW+255)/256, 256>>>(x, in_w, in_b);
    gemm_k<64,4,4><<<dim3(gHW,1,Bq),256>>>(rbin_w1,0, h0,(long)NF*HW,HW,
        t1,(long)NF*HW,HW, rbin_b1,0, nullptr,0,0, NF,HW,NF, 1, nullptr);
    gemm_k<64,4,4><<<dim3(gHW,1,Bq),256>>>(rbin_w2,0, t1,(long)NF*HW,HW,
        hrb,(long)NF*HW,HW, rbin_b2,0, h0,(long)NF*HW,HW, NF,HW,NF, 0, nullptr);
    pad_k<<<(Bq*NF*VOX+255)/256, 256>>>();

    // ---- scan: 4 injected-MLP steps
    for (int it=0; it<N_CALLS; it++){
        sobel_k<<<Bq*NF, 512, VOX*(int)sizeof(float)>>>();
        fold_k<<<dim3(192, Bq), 128>>>();
        // hh = lrelu(W1f @ p + b1f)   (inorm folded)
        gemm_k<64,4,4><<<dim3(gVOX,1,Bq),256>>>(w1f,(long)FH*FIN, p,(long)PROWS*VOX,VOX,
            hh,(long)FH*VOX,VOX, b1f,FH, nullptr,0,0, FH,VOX,FIN, 1, nullptr);
        // p[448:512] = lrelu(w2 @ hh + b2)
        gemm_k<64,4,4><<<dim3(gVOX,1,Bq),256>>>(dp+OFF_W2,PTOT, hh,(long)FH*VOX,VOX,
            p+(long)FIN*VOX,(long)PROWS*VOX,VOX, dp+OFF_B2,PTOT,
            nullptr,0,0, FH,VOX,FH, 1, nullptr);
        // carry += leak * val * sigmoid(gate) — BM=64, grid.y=2, 4 blocks/SM
        gemm_k<64,4,4><<<dim3(gVOX,2,Bq),256>>>(wcat,(long)FOUT*PROWS, p,(long)PROWS*VOX,VOX,
            carry,(long)NF*VOX,VOX, bcat,FOUT, nullptr,0,0, FOUT,VOX,PROWS, 2, leak);
    }

    // ---- rb2d_out + outc
    gemm_k<64,4,4><<<dim3(gHW,1,Bq),256>>>(rbout_w1,0, carry,(long)NF*VOX,VOX,
        t1,(long)NF*HW,HW, rbout_b1,0, nullptr,0,0, NF,HW,NF, 1, nullptr);
    gemm_k<64,4,4><<<dim3(gHW,1,Bq),256>>>(rbout_w2,0, t1,(long)NF*HW,HW,
        hrb,(long)NF*HW,HW, rbout_b2,0, carry,(long)NF*VOX,VOX, NF,HW,NF, 0, nullptr);
    gemm_k<64,4,4><<<dim3(gHW,4,Bq),256>>>(outc_w,0, hrb,(long)NF*HW,HW,
        f,(long)OUTC*HW,HW, outc_b,0, nullptr,0,0, OUTC,HW,NF, 0, nullptr);

    // ---- state features
    cf_k<<<Bq*NF, 256>>>();
    cfh_k<<<Bq*NF, 128>>>();
    cfw_k<<<Bq*NF, 128>>>();
    chw_k<<<(Bq*HW+255)/256, 256>>>();

    // ---- latent MLP head
    skinny_k<<<dim3((2*LATD+255)/256, 128), 256>>>(state, l1a_w, STATE, 2*LATD, 128);
    skinny_epi_k<<<(4*2*LATD+255)/256, 256>>>(128, 2*LATD, l1a_b, nullptr, s1, 1);
    skinny_k<<<dim3((LATD+255)/256, 128), 256>>>(state, l1s_w, STATE, LATD, 128);
    skinny_epi_k<<<(4*LATD+255)/256, 256>>>(128, LATD, nullptr, nullptr, s2, 0);
    skinny_k<<<dim3((LATD+255)/256, 32), 256>>>(s1, l1b_w, 2*LATD, LATD, 32);
    skinny_epi_k<<<(4*LATD+255)/256, 256>>>(32, LATD, l1b_b, s2, s3, 0);
    skinny_k<<<dim3((LATD+255)/256, 16), 256>>>(s3, l2a_w, LATD, LATD, 16);
    skinny_epi_k<<<(4*LATD+255)/256, 256>>>(16, LATD, l2a_b, nullptr, s1, 1);
    skinny_k<<<dim3((LATD+255)/256, 16), 256>>>(s1, l2b_w, LATD, LATD, 16);
    skinny_epi_k<<<(4*LATD+255)/256, 256>>>(16, LATD, l2b_b, s3, s2, 0);
    skinny_k<<<dim3((LATD+255)/256, 16), 256>>>(s2, lat_w, LATD, LATD, 16);
    skinny_epi_k<<<(4*LATD+255)/256, 256>>>(16, LATD, lat_b, nullptr, out, 0);
}

// round 16
// speedup vs baseline: 1.0899x; 1.0899x over previous
#include <cuda_runtime.h>
#include <math.h>

#define Bq 4
#define IMG 128
#define HW (IMG*IMG)          // 16384
#define NF 64
#define CUBE 26
#define VOX (CUBE*CUBE*CUBE)  // 17576
#define FIN 448
#define FH 64
#define FOUT 128
#define PROWS 512
#define OUTC 193
#define LATD 512
#define STATE 32832
#define PTOT 98688
#define N_CALLS 4

#define OFF_W1 0
#define OFF_B1 28672
#define OFF_W2 28736
#define OFF_B2 32832
#define OFF_W3 32896
#define OFF_B3 41088
#define OFF_WSH 41216
#define OFF_BSH 98560

// ---------------- scratch ------------------------------------------------------
__device__ float g_h0[Bq*NF*HW];
__device__ float g_t1[Bq*NF*HW];
__device__ float g_hrb[Bq*NF*HW];
__device__ float g_carry[Bq*NF*VOX];
__device__ float g_p[(long)Bq*PROWS*VOX];
__device__ float g_hh[Bq*NF*VOX];
__device__ float g_mean[Bq*FIN];
__device__ float g_inv[Bq*FIN];
__device__ float g_dp[Bq*PTOT];
__device__ float g_w1f[Bq*FH*FIN];
__device__ float g_b1f[Bq*FH];
__device__ float g_wcat[Bq*FOUT*PROWS];
__device__ float g_bcat[Bq*FOUT];
__device__ float g_f[Bq*OUTC*HW];
__device__ float g_state[Bq*STATE];
__device__ float g_part[1<<20];
__device__ float g_s1[Bq*2*LATD];
__device__ float g_s2[Bq*LATD];
__device__ float g_s3[Bq*LATD];

// ---------------- f32x2 helpers ----------------------------------------------
__device__ __forceinline__ unsigned long long pk2(float lo, float hi){
    unsigned long long r;
    asm("mov.b64 %0, {%1,%2};" : "=l"(r) : "f"(lo), "f"(hi));
    return r;
}
__device__ __forceinline__ void upk2(unsigned long long v, float& lo, float& hi){
    asm("mov.b64 {%0,%1}, %2;" : "=f"(lo), "=f"(hi) : "l"(v));
}
__device__ __forceinline__ void fma2(unsigned long long& d, unsigned long long a,
                                     unsigned long long b){
    asm("fma.rn.f32x2 %0, %1, %2, %0;" : "+l"(d) : "l"(a), "l"(b));
}
__device__ __forceinline__ float fast_sigmoid(float g){
    return __fdividef(1.f, 1.f + __expf(-g));
}

// ---------------- FFMA2 SGEMM, deferred A-store, 3-stage B pipeline --------------
// C[b](MxN) = epi( A[b](MxK) @ B[b](KxN) + bias ), BM=64, BN=128, BK=16, 256 thr.
// mode 0: store (+D);  mode 1: lrelu store;  mode 2: gated carry accumulate
// (wcat rows interleaved: row 2g = val g, row 2g+1 = gate g).
template<int BM, int TM, int MB>
__global__ void __launch_bounds__(256, MB) gemm_k(
    const float* __restrict__ A, long sA,
    const float* __restrict__ Bm, long sB, int ldB,
    float* __restrict__ C, long sC, int ldC,
    const float* __restrict__ bias, long sBias,
    const float* __restrict__ D, long sD, int ldD,
    int M, int N, int K, int mode,
    const float* __restrict__ leakp)
{
    constexpr int BK = 16;
    constexpr int APAD = BM + 4;
    constexpr int APT = BM/64;
    __shared__ __align__(16) float As[2][BK][APAD];
    __shared__ __align__(16) float Bs[3][BK][128];

    int b = blockIdx.z;
    A  += (long)b*sA;
    Bm += (long)b*sB;
    C  += (long)b*sC;
    const float* biasb = bias ? bias + (long)b*sBias : nullptr;
    const float* Db    = D    ? D    + (long)b*sD    : nullptr;

    int n0 = blockIdx.x*128;
    int m0 = blockIdx.y*BM;
    int tid = threadIdx.x;
    int tx = tid & 15, ty = tid >> 4;

    unsigned long long acc[TM][4];
#pragma unroll
    for (int i=0;i<TM;i++)
#pragma unroll
        for (int j=0;j<4;j++) acc[i][j] = 0ULL;

    int nk = K / BK;
    float4 ra[APT];

    auto ldAr = [&](int kt){
#pragma unroll
        for (int c=0;c<APT;c++){
            int q = tid + c*256;
            int row = q >> 2, ks = (q & 3)*4;
            int m = m0 + row;
            ra[c] = (m < M) ? *(const float4*)(A + (long)m*K + kt*BK + ks)
                            : make_float4(0.f,0.f,0.f,0.f);
        }
    };
    auto stAr = [&](int bw){
#pragma unroll
        for (int c=0;c<APT;c++){
            int q = tid + c*256;
            int row = q >> 2, ks = (q & 3)*4;
            As[bw][ks+0][row] = ra[c].x;
            As[bw][ks+1][row] = ra[c].y;
            As[bw][ks+2][row] = ra[c].z;
            As[bw][ks+3][row] = ra[c].w;
        }
    };
    auto ldBa = [&](int st, int kt){
#pragma unroll
        for (int c=0;c<2;c++){
            int q = tid + c*256;
            int k = q >> 5, seg = q & 31;
            int n = n0 + seg*4;
            const float* src = Bm + (long)(kt*BK+k)*ldB + n;
            int sz = 16;
            if (n >= N){ sz = 0; src = Bm; }
            unsigned dst = (unsigned)__cvta_generic_to_shared(&Bs[st][k][seg*4]);
            asm volatile("cp.async.cg.shared.global [%0], [%1], 16, %2;"
                         :: "r"(dst), "l"(src), "r"(sz));
        }
    };

    // prologue: B tiles 0 and 1 in flight, A tile 0 in smem
    ldAr(0);
    ldBa(0, 0);
    asm volatile("cp.async.commit_group;");
    if (nk > 1) ldBa(1, 1);
    asm volatile("cp.async.commit_group;");
    stAr(0);

    int buf = 0;
    int st = 0;
    for (int kt=0; kt<nk; kt++){
        asm volatile("cp.async.wait_group 1;");
        __syncthreads();
        bool more = (kt+1 < nk);
        if (more) ldAr(kt+1);
        if (kt+2 < nk){
            int st2 = st+2; if (st2 >= 3) st2 -= 3;
            ldBa(st2, kt+2);
        }
        asm volatile("cp.async.commit_group;");
#pragma unroll
        for (int kk=0; kk<BK; kk++){
            float a[TM];
            *(float4*)&a[0] = *(const float4*)&As[buf][kk][ty*TM];
            if (TM == 8)
                *(float4*)&a[4] = *(const float4*)&As[buf][kk][ty*TM+4];
            ulonglong2 bp01 = *(const ulonglong2*)&Bs[st][kk][tx*4];
            ulonglong2 bp23 = *(const ulonglong2*)&Bs[st][kk][64 + tx*4];
#pragma unroll
            for (int i=0;i<TM;i++){
                unsigned long long ap = pk2(a[i], a[i]);
                fma2(acc[i][0], ap, bp01.x);
                fma2(acc[i][1], ap, bp01.y);
                fma2(acc[i][2], ap, bp23.x);
                fma2(acc[i][3], ap, bp23.y);
            }
        }
        if (more) stAr(buf^1);
        buf ^= 1;
        st++; if (st >= 3) st = 0;
    }

    float cv[TM][8];
#pragma unroll
    for (int i=0;i<TM;i++)
#pragma unroll
        for (int j=0;j<4;j++) upk2(acc[i][j], cv[i][2*j], cv[i][2*j+1]);

    if (mode == 2){
        float lk = fminf(fmaxf(leakp[0], 0.001f), 1000.f);
#pragma unroll
        for (int i=0;i<TM;i+=2){
            int m = m0 + ty*TM + i;
            int gg = m >> 1;
            float bv = biasb[m], bgt = biasb[m+1];
#pragma unroll
            for (int h=0;h<2;h++){
                int n = n0 + h*64 + tx*4;
                if (n < N){
                    float* cp = C + (long)gg*ldC + n;
                    float4 c = *(float4*)cp;
                    float vv[4], gv[4];
#pragma unroll
                    for (int e=0;e<4;e++){
                        vv[e] = cv[i][h*4+e]   + bv;
                        gv[e] = cv[i+1][h*4+e] + bgt;
                    }
                    c.x += lk*vv[0]*fast_sigmoid(gv[0]);
                    c.y += lk*vv[1]*fast_sigmoid(gv[1]);
                    c.z += lk*vv[2]*fast_sigmoid(gv[2]);
                    c.w += lk*vv[3]*fast_sigmoid(gv[3]);
                    *(float4*)cp = c;
                }
            }
        }
    } else {
#pragma unroll
        for (int i=0;i<TM;i++){
            int m = m0 + ty*TM + i;
            if (m >= M) continue;
            float bvv = biasb ? biasb[m] : 0.f;
#pragma unroll
            for (int h=0;h<2;h++){
                int n = n0 + h*64 + tx*4;
                if (n < N){
                    float4 v = make_float4(cv[i][h*4+0]+bvv, cv[i][h*4+1]+bvv,
                                           cv[i][h*4+2]+bvv, cv[i][h*4+3]+bvv);
                    if (Db){
                        float4 d = *(const float4*)(Db + (long)m*ldD + n);
                        v.x += d.x; v.y += d.y; v.z += d.z; v.w += d.w;
                    }
                    if (mode == 1){
                        v.x = v.x>0.f ? v.x : 0.2f*v.x;
                        v.y = v.y>0.f ? v.y : 0.2f*v.y;
                        v.z = v.z>0.f ? v.z : 0.2f*v.z;
                        v.w = v.w>0.f ? v.w : 0.2f*v.w;
                    }
                    *(float4*)(C + (long)m*ldC + n) = v;
                }
            }
        }
    }
}

// ---------------- elementwise ----------------------------------------------------
__global__ void conv1_k(const float* __restrict__ x, const float* __restrict__ w,
                        const float* __restrict__ bias){
    int idx = blockIdx.x*blockDim.x+threadIdx.x;
    if (idx >= Bq*NF*HW) return;
    int pix = idx % HW;
    int o = (idx/HW)%NF;
    int b = idx/(NF*HW);
    const float* xb = x + (long)b*3*HW + pix;
    g_h0[idx] = xb[0]*w[o*3] + xb[HW]*w[o*3+1] + xb[2*HW]*w[o*3+2] + bias[o];
}

__global__ void pad_k(){
    int idx = blockIdx.x*blockDim.x+threadIdx.x;
    if (idx >= Bq*NF*VOX) return;
    int v = idx % VOX;
    int bc = idx / VOX;
    g_carry[idx] = (v < HW) ? g_hrb[(long)bc*HW + v] : 0.f;
}

// ---------------- sobel + stats (R14 version: 512 threads, fp32 partials) --------
__global__ void sobel_k(){
    extern __shared__ float sc[];
    __shared__ float wsum[16][7], wsq[16][7];
    int bg = blockIdx.x;
    int gch = bg & 63, b = bg >> 6;
    int tid = threadIdx.x;
    int warp = tid >> 5, lane = tid & 31;
    const float* in = g_carry + (long)bg*VOX;
    for (int i=tid;i<VOX;i+=512) sc[i] = in[i];
    __syncthreads();

    auto at = [&](int d,int h,int w)->float{
        if ((unsigned)d>=CUBE || (unsigned)h>=CUBE || (unsigned)w>=CUBE) return 0.f;
        return sc[(d*CUBE+h)*CUBE+w];
    };

    float sum[7], sq[7];
#pragma unroll
    for (int t=0;t<7;t++){ sum[t]=0.f; sq[t]=0.f; }

    int ch[7] = {gch, 64+3*gch, 64+3*gch+1, 64+3*gch+2, 256+3*gch, 256+3*gch+1, 256+3*gch+2};
    float* pb = g_p + (long)b*PROWS*VOX;

    const float g5[5] = {-1.f, -0.70710678f, 0.f, 0.70710678f, 1.f};
    const float s5[3] = {0.70710678f, 1.f, 0.70710678f};

    for (int v=tid; v<VOX; v+=512){
        int d = v/(CUBE*CUBE);
        int r = v%(CUBE*CUBE);
        int h = r/CUBE, w = r%CUBE;

        float c = sc[v];
        float gx3 = at(d+1,h,w) - at(d-1,h,w);
        float gy3 = at(d,h+1,w) - at(d,h-1,w);
        float gz3 = at(d,h,w+1) - at(d,h,w-1);

        float gx5=0.f, gy5=0.f, gz5=0.f;
#pragma unroll
        for (int a=0;a<5;a++){
            if (a==2) continue;
            float ga = g5[a];
#pragma unroll
            for (int i=-1;i<=1;i++){
#pragma unroll
                for (int j=-1;j<=1;j++){
                    float sij = ga * s5[i+1]*s5[j+1];
                    gx5 += sij * at(d+a-2, h+i,   w+j);
                    gy5 += sij * at(d+i,   h+a-2, w+j);
                    gz5 += sij * at(d+i,   h+j,   w+a-2);
                }
            }
        }
        float o[7] = {c, gx3, gy3, gz3, gx5, gy5, gz5};
#pragma unroll
        for (int t=0;t<7;t++){
            pb[(long)ch[t]*VOX + v] = o[t];
            sum[t] += o[t];
            sq[t]  += o[t]*o[t];
        }
    }
#pragma unroll
    for (int t=0;t<7;t++){
#pragma unroll
        for (int off=16; off>0; off>>=1){
            sum[t] += __shfl_down_sync(0xffffffffu, sum[t], off);
            sq[t]  += __shfl_down_sync(0xffffffffu, sq[t],  off);
        }
        if (lane==0){ wsum[warp][t]=sum[t]; wsq[warp][t]=sq[t]; }
    }
    __syncthreads();
    if (tid < 7){
        double s=0.0, q=0.0;
        for (int w=0; w<16; w++){ s += (double)wsum[w][tid]; q += (double)wsq[w][tid]; }
        double m = s*(1.0/VOX);
        double var = q*(1.0/VOX) - m*m;
        g_mean[b*FIN + ch[tid]] = (float)m;
        g_inv [b*FIN + ch[tid]] = rsqrtf((float)var + 1e-5f);
    }
}

// ---------------- fold inorm into hypernet weights (interleaved wcat) -------------
__global__ void fold_k(){
    int r = blockIdx.x, b = blockIdx.y;
    int tid = threadIdx.x;
    __shared__ float red[128];
    const float* dpb = g_dp + (long)b*PTOT;
    const float* mv = g_mean + b*FIN;
    const float* iv = g_inv  + b*FIN;

    if (r < 64){
        int o = r;
        const float* wsrc = dpb + OFF_W1 + o*FIN;
        float* wd = g_w1f + ((long)b*FH + o)*FIN;
        float dot = 0.f;
        for (int i=tid;i<FIN;i+=128){
            float wi = wsrc[i]*iv[i];
            wd[i] = wi;
            dot += wi*mv[i];
        }
        red[tid]=dot; __syncthreads();
        for (int s=64;s>0;s>>=1){ if (tid<s) red[tid]+=red[tid+s]; __syncthreads(); }
        if (tid==0) g_b1f[b*FH+o] = dpb[OFF_B1+o] - red[0];
    } else {
        int rr = r - 64;                 // interleaved: row 2g=val g, 2g+1=gate g
        int gg = rr >> 1, e = rr & 1;
        int o = e*64 + gg;
        const float* wsh = dpb + OFF_WSH + o*FIN;
        const float* w3  = dpb + OFF_W3  + o*FH;
        float* wd = g_wcat + ((long)b*FOUT + rr)*PROWS;
        float dot = 0.f;
        for (int i=tid;i<FIN;i+=128){
            float wi = wsh[i]*iv[i];
            wd[i] = wi;
            dot += wi*mv[i];
        }
        if (tid < 64) wd[FIN + tid] = w3[tid];
        red[tid]=dot; __syncthreads();
        for (int s=64;s>0;s>>=1){ if (tid<s) red[tid]+=red[tid+s]; __syncthreads(); }
        if (tid==0) g_bcat[b*FOUT+rr] = dpb[OFF_B3+o] + dpb[OFF_BSH+o] - red[0];
    }
}

// ---------------- state assembly ---------------------------------------------------
__global__ void cf_k(){
    int bc = blockIdx.x;
    int b = bc/NF, c = bc%NF;
    const float* x = g_f + ((long)b*OUTC + c)*HW;
    __shared__ float red[256];
    int tid = threadIdx.x;
    float s=0.f;
    for (int i=tid;i<HW;i+=256) s += x[i];
    red[tid]=s; __syncthreads();
    for (int st=128;st>0;st>>=1){ if (tid<st) red[tid]+=red[tid+st]; __syncthreads(); }
    if (tid==0) g_state[(long)b*STATE + c] = red[0]*(1.f/HW);
}
__global__ void cfh_k(){
    int bc = blockIdx.x; int b = bc/NF, c = bc%NF;
    int h = threadIdx.x;
    const float* x = g_f + ((long)b*OUTC + 64 + c)*HW + h*IMG;
    float s=0.f;
    for (int w=0;w<IMG;w++) s += x[w];
    g_state[(long)b*STATE + 64 + c*IMG + h] = s*(1.f/IMG);
}
__global__ void cfw_k(){
    int bc = blockIdx.x; int b = bc/NF, c = bc%NF;
    int w = threadIdx.x;
    const float* x = g_f + ((long)b*OUTC + 128 + c)*HW + w;
    float s=0.f;
    for (int h=0;h<IMG;h++) s += x[h*IMG];
    g_state[(long)b*STATE + 8256 + c*IMG + w] = s*(1.f/IMG);
}
__global__ void chw_k(){
    int idx = blockIdx.x*blockDim.x+threadIdx.x;
    if (idx >= Bq*HW) return;
    int b = idx/HW, i = idx%HW;
    g_state[(long)b*STATE + 16448 + i] = g_f[((long)b*OUTC + 192)*HW + i];
}

// ---------------- skinny (M=4) GEMM: deterministic split-K ------------------------
__global__ void skinny_k(const float* __restrict__ X, const float* __restrict__ W,
                         int K, int O, int nCh){
    int o = blockIdx.x*256 + threadIdx.x;
    int ch = blockIdx.y;
    if (o >= O) return;
    long k0 = ((long)K*ch)/nCh, k1 = ((long)K*(ch+1))/nCh;
    float a0=0.f,a1=0.f,a2=0.f,a3=0.f;
    for (long k=k0;k<k1;k++){
        float wv = W[k*O + o];
        a0 += __ldg(&X[k])      *wv;
        a1 += __ldg(&X[K+k])    *wv;
        a2 += __ldg(&X[2L*K+k]) *wv;
        a3 += __ldg(&X[3L*K+k]) *wv;
    }
    long base = (long)ch*4*O + o;
    g_part[base]        = a0;
    g_part[base+O]      = a1;
    g_part[base+2L*O]   = a2;
    g_part[base+3L*O]   = a3;
}

__global__ void skinny_epi_k(int nCh, int O, const float* __restrict__ bias,
                             const float* __restrict__ add, float* __restrict__ out,
                             int act){
    int idx = blockIdx.x*256+threadIdx.x;
    if (idx >= 4*O) return;
    int b = idx/O, o = idx%O;
    float s=0.f;
    for (int ch=0;ch<nCh;ch++) s += g_part[(long)ch*4*O + (long)b*O + o];
    if (bias) s += bias[o];
    if (add)  s += add[idx];
    if (act)  s = s>0.f ? s : 0.2f*s;
    out[idx]=s;
}

// ---------------- launch orchestration ---------------------------------------------
extern "C" void kernel_launch(void* const* d_in, const int* in_sizes, int n_in,
                              void* d_out, int out_size)
{
    const float* x        = (const float*)d_in[0];
    const float* inj_lat  = (const float*)d_in[1];
    const float* in_w     = (const float*)d_in[2];
    const float* in_b     = (const float*)d_in[3];
    const float* rbin_w1  = (const float*)d_in[4];
    const float* rbin_b1  = (const float*)d_in[5];
    const float* rbin_w2  = (const float*)d_in[6];
    const float* rbin_b2  = (const float*)d_in[7];
    const float* leak     = (const float*)d_in[8];
    const float* hyper_w  = (const float*)d_in[9];
    const float* hyper_b  = (const float*)d_in[10];
    const float* rbout_w1 = (const float*)d_in[11];
    const float* rbout_b1 = (const float*)d_in[12];
    const float* rbout_w2 = (const float*)d_in[13];
    const float* rbout_b2 = (const float*)d_in[14];
    const float* outc_w   = (const float*)d_in[15];
    const float* outc_b   = (const float*)d_in[16];
    const float* l1a_w    = (const float*)d_in[17];
    const float* l1a_b    = (const float*)d_in[18];
    const float* l1b_w    = (const float*)d_in[19];
    const float* l1b_b    = (const float*)d_in[20];
    const float* l1s_w    = (const float*)d_in[21];
    const float* l2a_w    = (const float*)d_in[22];
    const float* l2a_b    = (const float*)d_in[23];
    const float* l2b_w    = (const float*)d_in[24];
    const float* l2b_b    = (const float*)d_in[25];
    const float* lat_w    = (const float*)d_in[26];
    const float* lat_b    = (const float*)d_in[27];
    float* out = (float*)d_out;

    float *h0, *t1, *hrb, *carry, *p, *hh, *dp, *f, *state, *s1, *s2, *s3;
    float *w1f, *b1f, *wcat, *bcat;
    cudaGetSymbolAddress((void**)&h0,    g_h0);
    cudaGetSymbolAddress((void**)&t1,    g_t1);
    cudaGetSymbolAddress((void**)&hrb,   g_hrb);
    cudaGetSymbolAddress((void**)&carry, g_carry);
    cudaGetSymbolAddress((void**)&p,     g_p);
    cudaGetSymbolAddress((void**)&hh,    g_hh);
    cudaGetSymbolAddress((void**)&dp,    g_dp);
    cudaGetSymbolAddress((void**)&f,     g_f);
    cudaGetSymbolAddress((void**)&state, g_state);
    cudaGetSymbolAddress((void**)&s1,    g_s1);
    cudaGetSymbolAddress((void**)&s2,    g_s2);
    cudaGetSymbolAddress((void**)&s3,    g_s3);
    cudaGetSymbolAddress((void**)&w1f,   g_w1f);
    cudaGetSymbolAddress((void**)&b1f,   g_b1f);
    cudaGetSymbolAddress((void**)&wcat,  g_wcat);
    cudaGetSymbolAddress((void**)&bcat,  g_bcat);

    cudaFuncSetAttribute(sobel_k, cudaFuncAttributeMaxDynamicSharedMemorySize,
                         VOX*(int)sizeof(float));

    const int gHW  = HW/128;            // 128
    const int gVOX = (VOX+127)/128;     // 138

    // ---- hypernetwork
    skinny_k<<<dim3((PTOT+255)/256, 2), 256>>>(inj_lat, hyper_w, LATD, PTOT, 2);
    skinny_epi_k<<<(4*PTOT+255)/256, 256>>>(2, PTOT, hyper_b, nullptr, dp, 0);

    // ---- input conv1x1 + rb2d_in
    conv1_k<<<(Bq*NF*HW+255)/256, 256>>>(x, in_w, in_b);
    gemm_k<64,4,4><<<dim3(gHW,1,Bq),256>>>(rbin_w1,0, h0,(long)NF*HW,HW,
        t1,(long)NF*HW,HW, rbin_b1,0, nullptr,0,0, NF,HW,NF, 1, nullptr);
    gemm_k<64,4,4><<<dim3(gHW,1,Bq),256>>>(rbin_w2,0, t1,(long)NF*HW,HW,
        hrb,(long)NF*HW,HW, rbin_b2,0, h0,(long)NF*HW,HW, NF,HW,NF, 0, nullptr);
    pad_k<<<(Bq*NF*VOX+255)/256, 256>>>();

    // ---- scan: 4 injected-MLP steps
    for (int it=0; it<N_CALLS; it++){
        sobel_k<<<Bq*NF, 512, VOX*(int)sizeof(float)>>>();
        fold_k<<<dim3(192, Bq), 128>>>();
        // hh = lrelu(W1f @ p + b1f)   (inorm folded)
        gemm_k<64,4,4><<<dim3(gVOX,1,Bq),256>>>(w1f,(long)FH*FIN, p,(long)PROWS*VOX,VOX,
            hh,(long)FH*VOX,VOX, b1f,FH, nullptr,0,0, FH,VOX,FIN, 1, nullptr);
        // p[448:512] = lrelu(w2 @ hh + b2)
        gemm_k<64,4,4><<<dim3(gVOX,1,Bq),256>>>(dp+OFF_W2,PTOT, hh,(long)FH*VOX,VOX,
            p+(long)FIN*VOX,(long)PROWS*VOX,VOX, dp+OFF_B2,PTOT,
            nullptr,0,0, FH,VOX,FH, 1, nullptr);
        // carry += leak * val * sigmoid(gate) — BM=64, grid.y=2, 4 blocks/SM
        gemm_k<64,4,4><<<dim3(gVOX,2,Bq),256>>>(wcat,(long)FOUT*PROWS, p,(long)PROWS*VOX,VOX,
            carry,(long)NF*VOX,VOX, bcat,FOUT, nullptr,0,0, FOUT,VOX,PROWS, 2, leak);
    }

    // ---- rb2d_out + outc
    gemm_k<64,4,4><<<dim3(gHW,1,Bq),256>>>(rbout_w1,0, carry,(long)NF*VOX,VOX,
        t1,(long)NF*HW,HW, rbout_b1,0, nullptr,0,0, NF,HW,NF, 1, nullptr);
    gemm_k<64,4,4><<<dim3(gHW,1,Bq),256>>>(rbout_w2,0, t1,(long)NF*HW,HW,
        hrb,(long)NF*HW,HW, rbout_b2,0, carry,(long)NF*VOX,VOX, NF,HW,NF, 0, nullptr);
    gemm_k<64,4,4><<<dim3(gHW,4,Bq),256>>>(outc_w,0, hrb,(long)NF*HW,HW,
        f,(long)OUTC*HW,HW, outc_b,0, nullptr,0,0, OUTC,HW,NF, 0, nullptr);

    // ---- state features
    cf_k<<<Bq*NF, 256>>>();
    cfh_k<<<Bq*NF, 128>>>();
    cfw_k<<<Bq*NF, 128>>>();
    chw_k<<<(Bq*HW+255)/256, 256>>>();

    // ---- latent MLP head
    skinny_k<<<dim3((2*LATD+255)/256, 128), 256>>>(state, l1a_w, STATE, 2*LATD, 128);
    skinny_epi_k<<<(4*2*LATD+255)/256, 256>>>(128, 2*LATD, l1a_b, nullptr, s1, 1);
    skinny_k<<<dim3((LATD+255)/256, 128), 256>>>(state, l1s_w, STATE, LATD, 128);
    skinny_epi_k<<<(4*LATD+255)/256, 256>>>(128, LATD, nullptr, nullptr, s2, 0);
    skinny_k<<<dim3((LATD+255)/256, 32), 256>>>(s1, l1b_w, 2*LATD, LATD, 32);
    skinny_epi_k<<<(4*LATD+255)/256, 256>>>(32, LATD, l1b_b, s2, s3, 0);
    skinny_k<<<dim3((LATD+255)/256, 16), 256>>>(s3, l2a_w, LATD, LATD, 16);
    skinny_epi_k<<<(4*LATD+255)/256, 256>>>(16, LATD, l2a_b, nullptr, s1, 1);
    skinny_k<<<dim3((LATD+255)/256, 16), 256>>>(s1, l2b_w, LATD, LATD, 16);
    skinny_epi_k<<<(4*LATD+255)/256, 256>>>(16, LATD, l2b_b, s3, s2, 0);
    skinny_k<<<dim3((LATD+255)/256, 16), 256>>>(s2, lat_w, LATD, LATD, 16);
    skinny_epi_k<<<(4*LATD+255)/256, 256>>>(16, LATD, lat_b, nullptr, out, 0);
}